// round 14
// baseline (speedup 1.0000x reference)
#include <cuda_runtime.h>
#include <cstdint>

// Segment-mean over sorted segment ids.
// feats: [N, 128] f32, segment_ids: [N] i32 (sorted ascending), out: [S, 128] f32.
//
//   1) boundary_kernel: vectorized linear scan, one thread per 8 rows
//      (2x int4) fills g_seg_bounds; every entry written exactly once
//      (empty segments included). Signals PDL completion after its writes.
//   2) seg_mean_kernel: one 128-thread CTA per segment (16 CTAs/SM for
//      fine-grained dispatch + tail balance), 4x-unrolled evict-first
//      float4 streaming, 4-way smem reduction epilogue.

static constexpr int D = 128;          // feature dim
static constexpr int D4 = D / 4;       // 32 float4 per row
static constexpr int THREADS = 128;
static constexpr int NGROUPS = THREADS / 32;  // 4 rows in flight
static constexpr int MAX_SEGS = 1 << 20;

__device__ int g_seg_bounds[MAX_SEGS + 1];

__global__ void boundary_kernel(const int* __restrict__ seg_ids, int N, int S) {
    const int t = blockIdx.x * blockDim.x + threadIdx.x;
    const int base = t * 8;

    if (base < N) {
        if (base + 8 <= N) {
            // Fast path: two int4 loads cover ids[base..base+7].
            const int4 v0 = *reinterpret_cast<const int4*>(seg_ids + base);
            const int4 v1 = *reinterpret_cast<const int4*>(seg_ids + base + 4);
            int id[8] = {v0.x, v0.y, v0.z, v0.w, v1.x, v1.y, v1.z, v1.w};

            int prev;
            if (base == 0) {
                // head: segments 0..id[0] start at row 0
                for (int q = 0; q <= id[0]; q++) g_seg_bounds[q] = 0;
                prev = id[0];
            } else {
                prev = seg_ids[base - 1];   // L1-hit from neighbor's vector
            }

            #pragma unroll
            for (int j = 0; j < 8; j++) {
                if (prev != id[j])
                    for (int q = prev + 1; q <= id[j]; q++) g_seg_bounds[q] = base + j;
                prev = id[j];
            }

            if (base + 8 == N) {
                // tail: segments id[7]+1..S "start" at N (empty) + end sentinel
                for (int q = id[7] + 1; q <= S; q++) g_seg_bounds[q] = N;
            }
        } else {
            // Tail remainder (N not divisible by 8): scalar walk.
            int prev;
            if (base == 0) {
                const int id0 = seg_ids[0];
                for (int q = 0; q <= id0; q++) g_seg_bounds[q] = 0;
                prev = id0;
            } else {
                prev = seg_ids[base - 1];
            }
            for (int i = base; i < N; i++) {
                const int cur = seg_ids[i];
                if (prev != cur) for (int q = prev + 1; q <= cur; q++) g_seg_bounds[q] = i;
                prev = cur;
            }
            for (int q = prev + 1; q <= S; q++) g_seg_bounds[q] = N;
        }
    }

    // Allow the dependent seg_mean grid to begin launching.
    cudaTriggerProgrammaticLaunchCompletion();
}

__global__ __launch_bounds__(THREADS)
void seg_mean_kernel(const float* __restrict__ feats,
                     float* __restrict__ out) {
    const int s = blockIdx.x;

    const int lane = threadIdx.x & 31;
    const int grp  = threadIdx.x >> 5;   // 0..3
    const float4* __restrict__ f4 = reinterpret_cast<const float4*>(feats);

    // Wait for boundary_kernel's writes (no-op without PDL).
    cudaGridDependencySynchronize();

    const int start = g_seg_bounds[s];
    const int end   = g_seg_bounds[s + 1];
    const int cnt   = end - start;

    float4 acc = make_float4(0.f, 0.f, 0.f, 0.f);

    // 4x unrolled strided walk: grp g handles rows start+g, start+g+4, ...
    // Each lane loads one float4 (16B); a warp covers a full 512B row.
    // __ldcs = evict-first: feats are read exactly once.
    int r = start + grp;
    for (; r + 3 * NGROUPS < end; r += 4 * NGROUPS) {
        float4 a = __ldcs(&f4[(size_t)r * D4 + lane]);
        float4 b = __ldcs(&f4[(size_t)(r + NGROUPS) * D4 + lane]);
        float4 c = __ldcs(&f4[(size_t)(r + 2 * NGROUPS) * D4 + lane]);
        float4 d = __ldcs(&f4[(size_t)(r + 3 * NGROUPS) * D4 + lane]);
        acc.x += a.x; acc.y += a.y; acc.z += a.z; acc.w += a.w;
        acc.x += b.x; acc.y += b.y; acc.z += b.z; acc.w += b.w;
        acc.x += c.x; acc.y += c.y; acc.z += c.z; acc.w += c.w;
        acc.x += d.x; acc.y += d.y; acc.z += d.z; acc.w += d.w;
    }
    for (; r < end; r += NGROUPS) {
        float4 a = __ldcs(&f4[(size_t)r * D4 + lane]);
        acc.x += a.x; acc.y += a.y; acc.z += a.z; acc.w += a.w;
    }

    // Cross-group reduction: 4 groups x 32 lanes of float4 through smem.
    __shared__ float4 red[NGROUPS][D4];
    red[grp][lane] = acc;
    __syncthreads();

    if (grp == 0) {
        float4 t = red[0][lane];
        #pragma unroll
        for (int g = 1; g < NGROUPS; g++) {
            float4 v = red[g][lane];
            t.x += v.x; t.y += v.y; t.z += v.z; t.w += v.w;
        }
        const float inv = 1.0f / (float)(cnt > 0 ? cnt : 1);
        t.x *= inv; t.y *= inv; t.z *= inv; t.w *= inv;
        reinterpret_cast<float4*>(out)[(size_t)s * D4 + lane] = t;
    }
}

extern "C" void kernel_launch(void* const* d_in, const int* in_sizes, int n_in,
                              void* d_out, int out_size) {
    const float* feats   = (const float*)d_in[0];
    const int*   seg_ids = (const int*)d_in[1];
    float*       out     = (float*)d_out;

    const int N = in_sizes[0] / D;       // number of rows in feats
    const int S = out_size / D;          // number of segments

    const int bthreads = 256;
    const int nvec     = (N + 7) / 8;
    const int bblocks  = (nvec + bthreads - 1) / bthreads;
    boundary_kernel<<<bblocks, bthreads>>>(seg_ids, N, S);

    // Dependent launch with PDL (neutral but harmless; falls back cleanly).
    cudaLaunchConfig_t cfg = {};
    cfg.gridDim = dim3((unsigned)S);
    cfg.blockDim = dim3((unsigned)THREADS);
    cfg.dynamicSmemBytes = 0;
    cfg.stream = 0;
    cudaLaunchAttribute attrs[1];
    attrs[0].id = cudaLaunchAttributeProgrammaticStreamSerialization;
    attrs[0].val.programmaticStreamSerializationAllowed = 1;
    cfg.attrs = attrs;
    cfg.numAttrs = 1;

    cudaError_t e = cudaLaunchKernelEx(&cfg, seg_mean_kernel, feats, out);
    if (e != cudaSuccess) {
        (void)cudaGetLastError();  // clear sticky error state
        seg_mean_kernel<<<S, THREADS>>>(feats, out);
    }
}

// round 16
// speedup vs baseline: 1.0091x; 1.0091x over previous
#include <cuda_runtime.h>
#include <cstdint>

// Segment-mean over sorted segment ids.
// feats: [N, 128] f32, segment_ids: [N] i32 (sorted ascending), out: [S, 128] f32.
//
//   1) boundary_kernel: vectorized linear scan, one thread per 8 rows
//      (2x int4) fills g_seg_bounds; every entry written exactly once
//      (empty segments included). Signals PDL completion after its writes.
//   2) seg_mean_kernel: ONE WARP per segment (blockDim=32). A row is exactly
//      32 float4, so lane l privately accumulates column l across the
//      segment's rows — no smem, no barrier, no cross-warp reduction.
//      4x-unrolled evict-first float4 streaming over consecutive rows.

static constexpr int D = 128;          // feature dim
static constexpr int D4 = D / 4;       // 32 float4 per row
static constexpr int MAX_SEGS = 1 << 20;

__device__ int g_seg_bounds[MAX_SEGS + 1];

__global__ void boundary_kernel(const int* __restrict__ seg_ids, int N, int S) {
    const int t = blockIdx.x * blockDim.x + threadIdx.x;
    const int base = t * 8;

    if (base < N) {
        if (base + 8 <= N) {
            // Fast path: two int4 loads cover ids[base..base+7].
            const int4 v0 = *reinterpret_cast<const int4*>(seg_ids + base);
            const int4 v1 = *reinterpret_cast<const int4*>(seg_ids + base + 4);
            int id[8] = {v0.x, v0.y, v0.z, v0.w, v1.x, v1.y, v1.z, v1.w};

            int prev;
            if (base == 0) {
                // head: segments 0..id[0] start at row 0
                for (int q = 0; q <= id[0]; q++) g_seg_bounds[q] = 0;
                prev = id[0];
            } else {
                prev = seg_ids[base - 1];   // L1-hit from neighbor's vector
            }

            #pragma unroll
            for (int j = 0; j < 8; j++) {
                if (prev != id[j])
                    for (int q = prev + 1; q <= id[j]; q++) g_seg_bounds[q] = base + j;
                prev = id[j];
            }

            if (base + 8 == N) {
                // tail: segments id[7]+1..S "start" at N (empty) + end sentinel
                for (int q = id[7] + 1; q <= S; q++) g_seg_bounds[q] = N;
            }
        } else {
            // Tail remainder (N not divisible by 8): scalar walk.
            int prev;
            if (base == 0) {
                const int id0 = seg_ids[0];
                for (int q = 0; q <= id0; q++) g_seg_bounds[q] = 0;
                prev = id0;
            } else {
                prev = seg_ids[base - 1];
            }
            for (int i = base; i < N; i++) {
                const int cur = seg_ids[i];
                if (prev != cur) for (int q = prev + 1; q <= cur; q++) g_seg_bounds[q] = i;
                prev = cur;
            }
            for (int q = prev + 1; q <= S; q++) g_seg_bounds[q] = N;
        }
    }

    // Allow the dependent seg_mean grid to begin launching.
    cudaTriggerProgrammaticLaunchCompletion();
}

__global__ __launch_bounds__(32)
void seg_mean_kernel(const float* __restrict__ feats,
                     float* __restrict__ out) {
    const int s = blockIdx.x;
    const int lane = threadIdx.x;   // 0..31

    const float4* __restrict__ f4 = reinterpret_cast<const float4*>(feats);

    // Wait for boundary_kernel's writes (no-op without PDL).
    cudaGridDependencySynchronize();

    const int start = g_seg_bounds[s];
    const int end   = g_seg_bounds[s + 1];
    const int cnt   = end - start;

    float4 acc = make_float4(0.f, 0.f, 0.f, 0.f);

    // Lane l owns column l. 4x unrolled over consecutive rows: each unroll
    // iteration streams 4 rows x 512 B = 2 KB contiguous per warp.
    // __ldcs = evict-first: feats are read exactly once.
    int r = start;
    for (; r + 3 < end; r += 4) {
        float4 a = __ldcs(&f4[(size_t)r * D4 + lane]);
        float4 b = __ldcs(&f4[(size_t)(r + 1) * D4 + lane]);
        float4 c = __ldcs(&f4[(size_t)(r + 2) * D4 + lane]);
        float4 d = __ldcs(&f4[(size_t)(r + 3) * D4 + lane]);
        acc.x += a.x; acc.y += a.y; acc.z += a.z; acc.w += a.w;
        acc.x += b.x; acc.y += b.y; acc.z += b.z; acc.w += b.w;
        acc.x += c.x; acc.y += c.y; acc.z += c.z; acc.w += c.w;
        acc.x += d.x; acc.y += d.y; acc.z += d.z; acc.w += d.w;
    }
    for (; r < end; r++) {
        float4 a = __ldcs(&f4[(size_t)r * D4 + lane]);
        acc.x += a.x; acc.y += a.y; acc.z += a.z; acc.w += a.w;
    }

    // No reduction needed: lane's accumulator IS the output element.
    const float inv = 1.0f / (float)(cnt > 0 ? cnt : 1);
    acc.x *= inv; acc.y *= inv; acc.z *= inv; acc.w *= inv;
    reinterpret_cast<float4*>(out)[(size_t)s * D4 + lane] = acc;
}

extern "C" void kernel_launch(void* const* d_in, const int* in_sizes, int n_in,
                              void* d_out, int out_size) {
    const float* feats   = (const float*)d_in[0];
    const int*   seg_ids = (const int*)d_in[1];
    float*       out     = (float*)d_out;

    const int N = in_sizes[0] / D;       // number of rows in feats
    const int S = out_size / D;          // number of segments

    const int bthreads = 256;
    const int nvec     = (N + 7) / 8;
    const int bblocks  = (nvec + bthreads - 1) / bthreads;
    boundary_kernel<<<bblocks, bthreads>>>(seg_ids, N, S);

    // Dependent launch with PDL (neutral but harmless; falls back cleanly).
    cudaLaunchConfig_t cfg = {};
    cfg.gridDim = dim3((unsigned)S);
    cfg.blockDim = dim3(32u);
    cfg.dynamicSmemBytes = 0;
    cfg.stream = 0;
    cudaLaunchAttribute attrs[1];
    attrs[0].id = cudaLaunchAttributeProgrammaticStreamSerialization;
    attrs[0].val.programmaticStreamSerializationAllowed = 1;
    cfg.attrs = attrs;
    cfg.numAttrs = 1;

    cudaError_t e = cudaLaunchKernelEx(&cfg, seg_mean_kernel, feats, out);
    if (e != cudaSuccess) {
        (void)cudaGetLastError();  // clear sticky error state
        seg_mean_kernel<<<S, 32>>>(feats, out);
    }
}